// round 1
// baseline (speedup 1.0000x reference)
#include <cuda_runtime.h>

#define NV 64
#define NP 2016       // 64*63/2
#define NQ 504        // NP/4
#define TPB 256

__global__ __launch_bounds__(TPB) void score_kernel(
    const float* __restrict__ views,     // [B, 64, 7]
    const float* __restrict__ pairs,     // [B, 2016, 3]
    const float* __restrict__ s_a1,
    const float* __restrict__ s_a2,
    const float* __restrict__ s_gsd,
    const float* __restrict__ s_scale,
    const float* __restrict__ s_nrm,
    const float* __restrict__ s_dist,
    float* __restrict__ out)             // [B]
{
    const int b   = blockIdx.x;
    const int tid = threadIdx.x;

    __shared__ float w[NV];
    __shared__ float warpsum[TPB / 32];

    // Broadcast scalar params (L2/const-cached; negligible)
    const float a1 = *s_a1;
    const float a2 = *s_a2;
    const float inv_a1   = -0.5f / (a1 * a1);
    const float inv_a2   = -0.5f / (a2 * a2);
    const float gs = *s_gsd;   const float inv_gsd  = -0.5f / (gs * gs);
    const float sc = *s_scale; const float inv_sc   = -0.5f / (sc * sc);
    const float ns = *s_nrm;   const float inv_nrm  = -0.5f / (ns * ns);
    const float ds = *s_dist;  const float inv_dist = -0.5f / (ds * ds);
    const float TH = 20.0f / 90.0f;

    // Per-view combined weight: w[v] = mask * gsd * nrm * dist
    if (tid < NV) {
        const float* vr = views + ((size_t)b * NV + tid) * 7;
        float v0 = vr[0];
        float x4 = vr[4];
        float x5 = vr[5];
        float x6 = vr[6];
        float m  = (v0 == 1.0f) ? 1.0f : 0.0f;
        float x4sq = x4 * x4;
        float g = __expf((x4sq * x4sq) * inv_gsd);   // x^4
        float n = __expf((x5 * x5)     * inv_nrm);   // x^2
        float d = __expf((x6 * x6)     * inv_dist);  // x^2
        w[tid] = m * g * n * d;
    }
    __syncthreads();

    // Pairs: each thread handles 4 consecutive pairs (= 3 aligned float4s)
    const float4* pr = (const float4*)(pairs + (size_t)b * NP * 3);
    float acc = 0.0f;

    for (int q = tid; q < NQ; q += TPB) {
        float4 f0 = pr[3 * q + 0];
        float4 f1 = pr[3 * q + 1];
        float4 f2 = pr[3 * q + 2];

        float pm[4] = { (f0.x != 0.0f) ? 1.0f : 0.0f,
                        (f0.w != 0.0f) ? 1.0f : 0.0f,
                        (f1.z != 0.0f) ? 1.0f : 0.0f,
                        (f2.y != 0.0f) ? 1.0f : 0.0f };
        float av[4] = { f0.y, f1.x, f1.w, f2.z };
        float sv[4] = { f0.z, f1.y, f2.x, f2.w };

        // (i, j) for first pair of the quad via exact closed form.
        // off(i) = i*(127-i)/2; 16129 - 8*off(i) = (127-2i)^2 so sqrtf is
        // exact at row starts. Fix-up loops guard rounding in-row.
        int p0 = 4 * q;
        int i = (int)((127.0f - sqrtf((float)(16129 - 8 * p0))) * 0.5f);
        while (p0 < ((i * (127 - i)) >> 1)) --i;
        while (p0 >= (((i + 1) * (126 - i)) >> 1)) ++i;
        int j = p0 - ((i * (127 - i)) >> 1) + i + 1;

        #pragma unroll
        for (int k = 0; k < 4; ++k) {
            float a = av[k];
            float base;
            if (a == TH) {
                base = 0.0f;   // sigma=0, expo=0 -> exp(-inf) = 0
            } else {
                base = __expf((a * a) * ((a < TH) ? inv_a1 : inv_a2));
            }
            float s  = sv[k];
            float sscore = __expf((s * s) * inv_sc);
            acc += pm[k] * base * sscore * w[i] * w[j];

            // advance (i, j) to next pair
            ++j;
            if (j == NV) { ++i; j = i + 1; }
        }
    }

    // Block reduction
    #pragma unroll
    for (int o = 16; o > 0; o >>= 1)
        acc += __shfl_down_sync(0xffffffffu, acc, o);
    if ((tid & 31) == 0) warpsum[tid >> 5] = acc;
    __syncthreads();
    if (tid == 0) {
        float s = 0.0f;
        #pragma unroll
        for (int k = 0; k < TPB / 32; ++k) s += warpsum[k];
        out[b] = s;
    }
}

extern "C" void kernel_launch(void* const* d_in, const int* in_sizes, int n_in,
                              void* d_out, int out_size) {
    const float* views  = (const float*)d_in[0];
    const float* pairs  = (const float*)d_in[1];
    // d_in[2] = point_attribute (unused by reference computation)
    const float* a1     = (const float*)d_in[3];
    const float* a2     = (const float*)d_in[4];
    const float* gsd    = (const float*)d_in[5];
    const float* scale  = (const float*)d_in[6];
    const float* nrm    = (const float*)d_in[7];
    const float* dist   = (const float*)d_in[8];
    float* out = (float*)d_out;

    int B = in_sizes[0] / (NV * 7);
    score_kernel<<<B, TPB>>>(views, pairs, a1, a2, gsd, scale, nrm, dist, out);
}

// round 2
// speedup vs baseline: 1.1664x; 1.1664x over previous
#include <cuda_runtime.h>

#define NV 64
#define NP 2016       // 64*63/2
#define NQ 504        // NP/4
#define TPB 256

__global__ __launch_bounds__(TPB) void score_kernel(
    const float* __restrict__ views,     // [B, 64, 7]
    const float* __restrict__ pairs,     // [B, 2016, 3]
    const float* __restrict__ s_a1,
    const float* __restrict__ s_a2,
    const float* __restrict__ s_gsd,
    const float* __restrict__ s_scale,
    const float* __restrict__ s_nrm,
    const float* __restrict__ s_dist,
    float* __restrict__ out)             // [B]
{
    const int b   = blockIdx.x;
    const int tid = threadIdx.x;

    __shared__ float w[NV];
    __shared__ float warpsum[TPB / 32];

    // Scalar params, pre-scaled by log2(e) so exp(x) == exp2f(x * c) with
    // c folded into the coefficient (pure MUFU.EX2, no extra FMUL).
    const float L2E = 1.4426950408889634f;
    const float a1 = *s_a1;
    const float a2 = *s_a2;
    const float c_a1   = -0.5f * L2E / (a1 * a1);
    const float c_a2   = -0.5f * L2E / (a2 * a2);
    const float gs = *s_gsd;   const float c_gsd  = -0.5f * L2E / (gs * gs);
    const float sc = *s_scale; const float c_sc   = -0.5f * L2E / (sc * sc);
    const float ns = *s_nrm;   const float c_nrm  = -0.5f * L2E / (ns * ns);
    const float ds = *s_dist;  const float c_dist = -0.5f * L2E / (ds * ds);
    const float TH = 20.0f / 90.0f;

    // Per-view combined weight with a SINGLE exp2:
    // w[v] = mask * exp2(x4^4*c_gsd + x5^2*c_nrm + x6^2*c_dist)
    if (tid < NV) {
        const float* vr = views + ((size_t)b * NV + tid) * 7;
        float v0 = vr[0];
        float x4 = vr[4];
        float x5 = vr[5];
        float x6 = vr[6];
        float m  = (v0 == 1.0f) ? 1.0f : 0.0f;
        float x4sq = x4 * x4;
        float arg = fmaf(x4sq * x4sq, c_gsd,
                    fmaf(x5 * x5,     c_nrm,
                         (x6 * x6) *  c_dist));
        w[tid] = m * exp2f(arg);
    }
    __syncthreads();

    // Each thread handles up to 2 quads (8 pairs); all loads issued up front.
    const float4* pr = (const float4*)(pairs + (size_t)b * NP * 3);
    const int q0 = tid;
    const int q1 = tid + TPB;
    const bool has2 = (q1 < NQ);

    float4 A0 = pr[3 * q0 + 0];
    float4 A1 = pr[3 * q0 + 1];
    float4 A2 = pr[3 * q0 + 2];
    float4 B0, B1, B2;
    if (has2) {
        B0 = pr[3 * q1 + 0];
        B1 = pr[3 * q1 + 1];
        B2 = pr[3 * q1 + 2];
    }

    float acc = 0.0f;

    // Process a quad of 4 pairs starting at pair index p0 with data (f0,f1,f2)
    #define PROC_QUAD(p0_, f0, f1, f2)                                         \
    {                                                                          \
        int p0 = (p0_);                                                        \
        int i = (int)((127.0f - sqrtf((float)(16129 - 8 * p0))) * 0.5f);       \
        while (p0 < ((i * (127 - i)) >> 1)) --i;                               \
        while (p0 >= (((i + 1) * (126 - i)) >> 1)) ++i;                        \
        int j = p0 - ((i * (127 - i)) >> 1) + i + 1;                           \
        float pm[4] = { ((f0).x != 0.0f) ? 1.0f : 0.0f,                        \
                        ((f0).w != 0.0f) ? 1.0f : 0.0f,                        \
                        ((f1).z != 0.0f) ? 1.0f : 0.0f,                        \
                        ((f2).y != 0.0f) ? 1.0f : 0.0f };                      \
        float av[4] = { (f0).y, (f1).x, (f1).w, (f2).z };                      \
        float sv[4] = { (f0).z, (f1).y, (f2).x, (f2).w };                      \
        _Pragma("unroll")                                                      \
        for (int k = 0; k < 4; ++k) {                                          \
            float a = av[k];                                                   \
            float s = sv[k];                                                   \
            float m = (a == TH) ? 0.0f : pm[k];                                \
            float ca = (a < TH) ? c_a1 : c_a2;                                 \
            float arg = fmaf(a * a, ca, (s * s) * c_sc);                       \
            float e = exp2f(arg);              /* base * scale_score */        \
            acc = fmaf(m * e, w[i] * w[j], acc);                               \
            ++j;                                                               \
            if (j == NV) { ++i; j = i + 1; }                                   \
        }                                                                      \
    }

    PROC_QUAD(4 * q0, A0, A1, A2);
    if (has2) {
        PROC_QUAD(4 * q1, B0, B1, B2);
    }
    #undef PROC_QUAD

    // Block reduction
    #pragma unroll
    for (int o = 16; o > 0; o >>= 1)
        acc += __shfl_down_sync(0xffffffffu, acc, o);
    if ((tid & 31) == 0) warpsum[tid >> 5] = acc;
    __syncthreads();
    if (tid == 0) {
        float s = 0.0f;
        #pragma unroll
        for (int k = 0; k < TPB / 32; ++k) s += warpsum[k];
        out[b] = s;
    }
}

extern "C" void kernel_launch(void* const* d_in, const int* in_sizes, int n_in,
                              void* d_out, int out_size) {
    const float* views  = (const float*)d_in[0];
    const float* pairs  = (const float*)d_in[1];
    // d_in[2] = point_attribute (unused by reference computation)
    const float* a1     = (const float*)d_in[3];
    const float* a2     = (const float*)d_in[4];
    const float* gsd    = (const float*)d_in[5];
    const float* scale  = (const float*)d_in[6];
    const float* nrm    = (const float*)d_in[7];
    const float* dist   = (const float*)d_in[8];
    float* out = (float*)d_out;

    int B = in_sizes[0] / (NV * 7);
    score_kernel<<<B, TPB>>>(views, pairs, a1, a2, gsd, scale, nrm, dist, out);
}